// round 4
// baseline (speedup 1.0000x reference)
#include <cuda_runtime.h>

#define TT      65536
#define HID     128
#define G3      384
#define INS     96
#define LIN     32
#define CHUNK   16
#define NCHUNK  (TT / CHUNK)   // 4096
#define NPROD   147
#define NBLK    (NPROD + 1)    // 148

// 96 MB scratch for precomputed input gates, + chunk-ready flags
__device__ float g_ig[TT * G3];
__device__ int   g_flag[NCHUNK];

// ---------- f32x2 helpers ----------
static __device__ __forceinline__ unsigned long long pk2(float a, float b) {
    unsigned long long r;
    asm("mov.b64 %0, {%1,%2};" : "=l"(r) : "f"(a), "f"(b));
    return r;
}
static __device__ __forceinline__ void fma2(unsigned long long& d,
                                            unsigned long long a,
                                            unsigned long long b) {
    asm("fma.rn.f32x2 %0, %1, %2, %0;" : "+l"(d) : "l"(a), "l"(b));
}
static __device__ __forceinline__ unsigned long long add2(unsigned long long a,
                                                          unsigned long long b) {
    unsigned long long r;
    asm("add.rn.f32x2 %0, %1, %2;" : "=l"(r) : "l"(a), "l"(b));
    return r;
}
static __device__ __forceinline__ float lo_hi_sum(unsigned long long v) {
    float lo, hi;
    asm("mov.b64 {%0,%1}, %2;" : "=f"(lo), "=f"(hi) : "l"(v));
    return lo + hi;
}

// ---------- fast transcendentals (MUFU-based, ~1e-6 rel err) ----------
static __device__ __forceinline__ float fex2(float x) {
    float r; asm("ex2.approx.f32 %0, %1;" : "=f"(r) : "f"(x)); return r;
}
static __device__ __forceinline__ float frcp(float x) {
    float r; asm("rcp.approx.f32 %0, %1;" : "=f"(r) : "f"(x)); return r;
}
static __device__ __forceinline__ float sigmoid_f(float x) {
    // 1 / (1 + exp(-x)) ; exp(-x) = 2^(-x*log2e)
    return frcp(1.0f + fex2(-1.4426950408889634f * x));
}
static __device__ __forceinline__ float tanh_f(float x) {
    float ax = fabsf(x);
    float e  = fex2(-2.885390081777927f * ax);   // exp(-2*ax)
    float t  = (1.0f - e) * frcp(1.0f + e);
    return copysignf(t, x);
}

// ---------- clear flags each launch (graph-replay safe) ----------
__global__ void gru_clear_flags() {
    int i = blockIdx.x * blockDim.x + threadIdx.x;
    if (i < NCHUNK) g_flag[i] = 0;
}

// ---------- fused kernel: block 0 = sequential scan, blocks 1..147 = igates GEMM ----------
__global__ __launch_bounds__(G3, 1)
void gru_fused(const float* __restrict__ x_gru,   // (T, 96)
               const float* __restrict__ x_lin,   // (T, 32)
               const float* __restrict__ h_init,  // (128,)
               const float* __restrict__ w_ih,    // (384, 96)
               const float* __restrict__ w_hh,    // (384, 128)
               const float* __restrict__ b_ih,    // (384,)
               const float* __restrict__ b_nv,    // (128,)
               const float* __restrict__ lbias_p, // (1,)
               float* __restrict__ out)           // (T, 1)
{
    __shared__ __align__(16) float smem[1664];
    const int tid = threadIdx.x;

    if (blockIdx.x != 0) {
        // ===================== PRODUCER: igates = x_gru @ w_ih.T + b_ih =====================
        const int b   = blockIdx.x - 1;   // 0..146
        const int row = tid;              // 0..383
        float wreg[INS];
        {
            const float* wp = w_ih + row * INS;
            #pragma unroll
            for (int k = 0; k < INS; k++) wreg[k] = wp[k];
        }
        const float bih = b_ih[row];

        for (int c = b; c < NCHUNK; c += NPROD) {
            const int t0 = c * CHUNK;
            __syncthreads();  // smem reuse guard across chunks
            // load CHUNK rows of x (coalesced), transposed into smem: smem[k*17 + tt]
            for (int i = tid; i < CHUNK * INS; i += G3) {
                int ttl = i / INS, k = i % INS;
                smem[k * 17 + ttl] = x_gru[(t0 + ttl) * INS + k];
            }
            __syncthreads();

            float acc[CHUNK];
            #pragma unroll
            for (int ttl = 0; ttl < CHUNK; ttl++) acc[ttl] = bih;
            #pragma unroll
            for (int k = 0; k < INS; k++) {
                const float w = wreg[k];
                #pragma unroll
                for (int ttl = 0; ttl < CHUNK; ttl++)
                    acc[ttl] = fmaf(w, smem[k * 17 + ttl], acc[ttl]);
            }
            #pragma unroll
            for (int ttl = 0; ttl < CHUNK; ttl++)
                g_ig[(t0 + ttl) * G3 + row] = acc[ttl];

            __syncthreads();  // all threads' stores issued before the release
            if (tid == 0) {
                __threadfence();
                atomicExch(&g_flag[c], 1);
            }
        }
        return;
    }

    // ===================== SCAN (single persistent CTA) =====================
    float* sh_h  = smem;        // [128] hidden state
    float* s_z   = smem + 128;  // [128] update gate
    float* s_np  = smem + 256;  // [128] hn + b_n
    float* s_ign = smem + 384;  // [128] i_n

    // thread tid owns w_hh row tid, packed as 64 f32x2 values in registers
    unsigned long long w[64];
    {
        const float2* wr = reinterpret_cast<const float2*>(w_hh + tid * HID);
        #pragma unroll
        for (int i = 0; i < 64; i++) { float2 v = wr[i]; w[i] = pk2(v.x, v.y); }
    }

    if (tid < HID) sh_h[tid] = h_init[tid];
    float h_reg = (tid < HID) ? h_init[tid] : 0.0f;
    const float bn    = (tid >= 256) ? b_nv[tid - 256] : 0.0f;
    const float lbias = lbias_p[0];

    // wait for chunk 0 (covers steps 0 and 1 prefetch)
    {
        int f;
        const int* fp = &g_flag[0];
        do { asm volatile("ld.acquire.gpu.global.b32 %0, [%1];" : "=r"(f) : "l"(fp)); } while (f == 0);
    }
    __syncthreads();

    float ig0 = g_ig[0 * G3 + tid];
    float ig1 = g_ig[1 * G3 + tid];
    float xl0 = 0.0f, xl1 = 0.0f;
    if (tid < LIN) { xl0 = x_lin[tid]; xl1 = x_lin[LIN + tid]; }

    for (int t = 0; t < TT; t++) {
        // ---- phase A: hgate[tid] = dot(w_row, h) via f32x2, h broadcast from smem ----
        unsigned long long a0 = 0ull, a1 = 0ull, a2 = 0ull, a3 = 0ull;
        const ulonglong2* h4 = reinterpret_cast<const ulonglong2*>(sh_h);
        #pragma unroll
        for (int i = 0; i < 32; i += 2) {
            ulonglong2 p = h4[i];
            ulonglong2 q = h4[i + 1];
            fma2(a0, w[2 * i],     p.x);
            fma2(a1, w[2 * i + 1], p.y);
            fma2(a2, w[2 * i + 2], q.x);
            fma2(a3, w[2 * i + 3], q.y);
        }
        const float g  = lo_hi_sum(add2(add2(a0, a1), add2(a2, a3)));
        const float ig = ig0;
        ig0 = ig1;

        // prefetch igates for t+2 (flag-gated at chunk boundaries)
        const int tp = t + 2;
        if (tp < TT) {
            if ((tp & (CHUNK - 1)) == 0) {
                const int c = tp >> 4;
                int f;
                const int* fp = &g_flag[c];
                do { asm volatile("ld.acquire.gpu.global.b32 %0, [%1];" : "=r"(f) : "l"(fp)); } while (f == 0);
            }
            ig1 = g_ig[tp * G3 + tid];
        }

        // per-row post-processing (warp-uniform branches: warps 0-3 / 4-7 / 8-11)
        float r = 0.0f;
        if (tid < 128) {
            r = sigmoid_f(g + ig);          // reset gate, stays in register
        } else if (tid < 256) {
            s_z[tid - 128] = sigmoid_f(g + ig);
        } else {
            s_np[tid - 256]  = g + bn;      // hn + b_n (igate kept separate!)
            s_ign[tid - 256] = ig;          // i_n
        }
        __syncthreads();  // bar1: hgate-derived values published; all reads of sh_h done

        // ---- phase B: gate combine (threads 0..127) ----
        if (tid < 128) {
            const float n  = tanh_f(s_ign[tid] + r * s_np[tid]);
            const float z  = s_z[tid];
            const float hn = fmaf(z, h_reg - n, n);   // n + z*(h - n)
            h_reg = hn;
            sh_h[tid] = hn;
        }
        __syncthreads();  // bar2: new h visible to all

        // ---- output: warp 0, overlaps next step's matvec of other warps ----
        if (tid < LIN) {
            float p = h_reg * xl0;          // h_reg = h_new[tid] for tid < 32
            xl0 = xl1;
            xl1 = (tp < TT) ? x_lin[tp * LIN + tid] : 0.0f;
            p += __shfl_xor_sync(0xffffffffu, p, 16);
            p += __shfl_xor_sync(0xffffffffu, p, 8);
            p += __shfl_xor_sync(0xffffffffu, p, 4);
            p += __shfl_xor_sync(0xffffffffu, p, 2);
            p += __shfl_xor_sync(0xffffffffu, p, 1);
            if (tid == 0) out[t] = p + lbias;
        }
    }
}

extern "C" void kernel_launch(void* const* d_in, const int* in_sizes, int n_in,
                              void* d_out, int out_size) {
    const float* x_gru = (const float*)d_in[0];  // (65536, 96)
    const float* x_lin = (const float*)d_in[1];  // (65536, 32)
    const float* h0    = (const float*)d_in[2];  // (128,)
    const float* w_ih  = (const float*)d_in[3];  // (384, 96)
    const float* w_hh  = (const float*)d_in[4];  // (384, 128)
    const float* b_ih  = (const float*)d_in[5];  // (384,)
    const float* b_n   = (const float*)d_in[6];  // (128,)
    const float* lb    = (const float*)d_in[7];  // (1,)
    float* out = (float*)d_out;                  // (65536, 1)

    gru_clear_flags<<<(NCHUNK + 255) / 256, 256>>>();
    gru_fused<<<NBLK, G3>>>(x_gru, x_lin, h0, w_ih, w_hh, b_ih, b_n, lb, out);
}